// round 11
// baseline (speedup 1.0000x reference)
#include <cuda_runtime.h>
#include <cstdint>

// Problem constants
#define B_   8
#define L_   4096
#define H_   8
#define E_   64
#define WIN  128
#define MQ   128          // queries per CTA (8 warps x 16)
#define KR   256          // key rows per CTA: [q0-128, q0+128)
#define NTHR 256

// SMEM strides (floats) chosen for conflict-free mma fragment loads
#define KSTR 68           // K row stride: bank = (4*row + dim) % 32, bijective over frag
#define VSTR 72           // V row stride: bank = (8*row + e)   % 32, bijective over frag
#define QSTR 68

// SMEM layout (float offsets)
#define OFF_K 0
#define OFF_V (KR * KSTR)                 // 17408
#define OFF_Q (OFF_V + KR * VSTR)         // 35840
#define SM_FLOATS (OFF_Q + MQ * QSTR)     // 44544
#define SM_BYTES  (SM_FLOATS * 4)         // 178176

__device__ __forceinline__ uint32_t tf32_rna(float x) {
    uint32_t r;
    asm("cvt.rna.tf32.f32 %0, %1;" : "=r"(r) : "f"(x));
    return r;
}
__device__ __forceinline__ float ex2f(float x) {
    float y; asm("ex2.approx.ftz.f32 %0, %1;" : "=f"(y) : "f"(x)); return y;
}
// D = A(16x8 tf32) * B(8x8 tf32) + D, fp32 accumulate (sm_80 baseline feature)
__device__ __forceinline__ void mma_tf32(float d[4], const uint32_t a[4],
                                         uint32_t b0, uint32_t b1) {
    asm("mma.sync.aligned.m16n8k8.row.col.f32.tf32.tf32.f32 "
        "{%0,%1,%2,%3}, {%4,%5,%6,%7}, {%8,%9}, {%0,%1,%2,%3};"
        : "+f"(d[0]), "+f"(d[1]), "+f"(d[2]), "+f"(d[3])
        : "r"(a[0]), "r"(a[1]), "r"(a[2]), "r"(a[3]), "r"(b0), "r"(b1));
}

__global__ void __launch_bounds__(NTHR, 1)
local_attn_mma(const float* __restrict__ Q, const float* __restrict__ K,
               const float* __restrict__ V, float* __restrict__ O) {
    extern __shared__ float sm[];
    float* Ks = sm + OFF_K;
    float* Vs = sm + OFF_V;
    float* Qs = sm + OFF_Q;

    const int tid  = threadIdx.x;
    const int lane = tid & 31;
    const int wid  = tid >> 5;

    const int bid = blockIdx.x;           // 2048 = 8 * 8 * 32
    const int b   = bid >> 8;
    const int h   = (bid >> 5) & 7;
    const int q0  = (bid & 31) * MQ;
    const int kbase = q0 - WIN;

    // ---- cooperative loads, converting to tf32 at store time ----
    // Q tile [128][64]
    for (int idx = tid; idx < MQ * 16; idx += NTHR) {
        int r = idx >> 4, c = idx & 15;
        float4 v = *reinterpret_cast<const float4*>(
            Q + ((size_t)(b * L_ + q0 + r) * H_ + h) * E_ + c * 4);
        uint4 u = make_uint4(tf32_rna(v.x), tf32_rna(v.y), tf32_rna(v.z), tf32_rna(v.w));
        *reinterpret_cast<uint4*>(Qs + r * QSTR + c * 4) = u;
    }
    // K tile [256][64], zero-fill rows with key < 0
    for (int idx = tid; idx < KR * 16; idx += NTHR) {
        int r = idx >> 4, c = idx & 15;
        int kg = kbase + r;
        float4 v = make_float4(0.f, 0.f, 0.f, 0.f);
        if (kg >= 0)
            v = *reinterpret_cast<const float4*>(
                K + ((size_t)(b * L_ + kg) * H_ + h) * E_ + c * 4);
        uint4 u = make_uint4(tf32_rna(v.x), tf32_rna(v.y), tf32_rna(v.z), tf32_rna(v.w));
        *reinterpret_cast<uint4*>(Ks + r * KSTR + c * 4) = u;
    }
    // V tile [256][64]
    for (int idx = tid; idx < KR * 16; idx += NTHR) {
        int r = idx >> 4, c = idx & 15;
        int kg = kbase + r;
        float4 v = make_float4(0.f, 0.f, 0.f, 0.f);
        if (kg >= 0)
            v = *reinterpret_cast<const float4*>(
                V + ((size_t)(b * L_ + kg) * H_ + h) * E_ + c * 4);
        uint4 u = make_uint4(tf32_rna(v.x), tf32_rna(v.y), tf32_rna(v.z), tf32_rna(v.w));
        *reinterpret_cast<uint4*>(Vs + r * VSTR + c * 4) = u;
    }
    __syncthreads();

    const int g = lane >> 2;              // group id (row within fragment)
    const int t = lane & 3;               // thread-in-group (col pair id)

    // ---- Q A-fragments for this warp's 16 queries (rows 16*wid .. +15) ----
    // a0=(g,t) a1=(g+8,t) a2=(g,t+4) a3=(g+8,t+4) within [16 rows][8 dims/kstep]
    uint32_t qa[8][4];
    {
        const uint32_t* Qu = reinterpret_cast<const uint32_t*>(Qs);
        int rbase = (16 * wid + g) * QSTR;
        #pragma unroll
        for (int ks = 0; ks < 8; ks++) {
            int c0 = 8 * ks + t;
            qa[ks][0] = Qu[rbase + c0];
            qa[ks][1] = Qu[rbase + 8 * QSTR + c0];
            qa[ks][2] = Qu[rbase + c0 + 4];
            qa[ks][3] = Qu[rbase + 8 * QSTR + c0 + 4];
        }
    }

    float oacc[8][4];
    #pragma unroll
    for (int f = 0; f < 8; f++)
        #pragma unroll
        for (int i = 0; i < 4; i++) oacc[f][i] = 0.f;

    float l0 = 0.f, l1 = 0.f;
    const int jmin  = (q0 == 0) ? WIN : 0;          // keys < 0 masked (first tile only)
    const int qloc0 = 16 * wid + g;
    const int qloc1 = qloc0 + 8;
    const float cexp = 0.18033688011112042f;        // log2(e) / 8

    const uint32_t* Ku = reinterpret_cast<const uint32_t*>(Ks);
    const uint32_t* Vu = reinterpret_cast<const uint32_t*>(Vs);

    // ---- main loop: 18 n-steps of 8 keys covering this warp's band ----
    const int ns_lo = 2 * wid;
    #pragma unroll 1
    for (int ns = ns_lo; ns < ns_lo + 18; ns++) {
        const int j0 = ns * 8;

        // QK: S[16,8] over K=64, split into two 4-deep chains for ILP
        float sa[4] = {0.f, 0.f, 0.f, 0.f};
        float sb[4] = {0.f, 0.f, 0.f, 0.f};
        {
            int kr = (j0 + g) * KSTR + t;            // B: b0=(k=t, n=g), b1=(k=t+4, n=g)
            #pragma unroll
            for (int ks = 0; ks < 4; ks++)
                mma_tf32(sa, qa[ks], Ku[kr + 8 * ks], Ku[kr + 8 * ks + 4]);
            #pragma unroll
            for (int ks = 4; ks < 8; ks++)
                mma_tf32(sb, qa[ks], Ku[kr + 8 * ks], Ku[kr + 8 * ks + 4]);
        }

        // masked exp2 softmax numerators (scores bounded => no running max needed)
        // C layout: c0=(g, 2t) c1=(g, 2t+1) c2=(g+8, 2t) c3=(g+8, 2t+1)
        const int jc0 = j0 + 2 * t, jc1 = jc0 + 1;
        float p0 = (jc0 > qloc0 && jc0 <= qloc0 + WIN && jc0 >= jmin)
                     ? ex2f((sa[0] + sb[0]) * cexp) : 0.f;
        float p1 = (jc1 > qloc0 && jc1 <= qloc0 + WIN && jc1 >= jmin)
                     ? ex2f((sa[1] + sb[1]) * cexp) : 0.f;
        float p2 = (jc0 > qloc1 && jc0 <= qloc1 + WIN && jc0 >= jmin)
                     ? ex2f((sa[2] + sb[2]) * cexp) : 0.f;
        float p3 = (jc1 > qloc1 && jc1 <= qloc1 + WIN && jc1 >= jmin)
                     ? ex2f((sa[3] + sb[3]) * cexp) : 0.f;
        l0 += p0 + p1;
        l1 += p2 + p3;

        // permute C layout (keys 2t,2t+1) -> A layout (keys t, t+4) within quads
        const int srcA = (lane & ~3) | (t >> 1);
        const int srcB = srcA + 2;
        float x0 = __shfl_sync(0xFFFFFFFFu, p0, srcA);
        float y0 = __shfl_sync(0xFFFFFFFFu, p1, srcA);
        float x1 = __shfl_sync(0xFFFFFFFFu, p2, srcA);
        float y1 = __shfl_sync(0xFFFFFFFFu, p3, srcA);
        float x2 = __shfl_sync(0xFFFFFFFFu, p0, srcB);
        float y2 = __shfl_sync(0xFFFFFFFFu, p1, srcB);
        float x3 = __shfl_sync(0xFFFFFFFFu, p2, srcB);
        float y3 = __shfl_sync(0xFFFFFFFFu, p3, srcB);
        const bool odd = (t & 1);
        uint32_t pa[4];
        pa[0] = tf32_rna(odd ? y0 : x0);
        pa[1] = tf32_rna(odd ? y1 : x1);
        pa[2] = tf32_rna(odd ? y2 : x2);
        pa[3] = tf32_rna(odd ? y3 : x3);

        // PV: O[16,64] += P[16,8] * V[8,64]; B: b0=(k=t, n=g), b1=(k=t+4, n=g)
        {
            int vr0 = (j0 + t) * VSTR + g;
            int vr1 = (j0 + t + 4) * VSTR + g;
            #pragma unroll
            for (int f = 0; f < 8; f++)
                mma_tf32(oacc[f], pa, Vu[vr0 + 8 * f], Vu[vr1 + 8 * f]);
        }
    }

    // ---- row-sum reduction across the lane quad, normalize, store ----
    l0 += __shfl_xor_sync(0xFFFFFFFFu, l0, 1);
    l0 += __shfl_xor_sync(0xFFFFFFFFu, l0, 2);
    l1 += __shfl_xor_sync(0xFFFFFFFFu, l1, 1);
    l1 += __shfl_xor_sync(0xFFFFFFFFu, l1, 2);
    const float inv0 = 1.0f / l0;
    const float inv1 = 1.0f / l1;

    float* o0 = O + ((size_t)(b * L_ + q0 + qloc0) * H_ + h) * E_;
    float* o1 = O + ((size_t)(b * L_ + q0 + qloc1) * H_ + h) * E_;
    #pragma unroll
    for (int f = 0; f < 8; f++) {
        int e = 8 * f + 2 * t;
        *reinterpret_cast<float2*>(o0 + e) =
            make_float2(oacc[f][0] * inv0, oacc[f][1] * inv0);
        *reinterpret_cast<float2*>(o1 + e) =
            make_float2(oacc[f][2] * inv1, oacc[f][3] * inv1);
    }
}

extern "C" void kernel_launch(void* const* d_in, const int* in_sizes, int n_in,
                              void* d_out, int out_size) {
    const float* Q = (const float*)d_in[0];
    const float* K = (const float*)d_in[1];
    const float* V = (const float*)d_in[2];
    float* O = (float*)d_out;

    cudaFuncSetAttribute(local_attn_mma,
                         cudaFuncAttributeMaxDynamicSharedMemorySize, SM_BYTES);

    dim3 grid(B_ * H_ * (L_ / MQ));   // 2048 CTAs
    dim3 block(NTHR);
    local_attn_mma<<<grid, block, SM_BYTES>>>(Q, K, V, O);
}

// round 12
// speedup vs baseline: 2.3816x; 2.3816x over previous
#include <cuda_runtime.h>
#include <cstdint>

// Problem constants
#define B_   8
#define L_   4096
#define H_   8
#define E_   64
#define WIN  128
#define MQ   128          // queries per CTA (8 warps x 16)
#define KR   256          // key rows per CTA: [q0-128, q0+128)
#define NTHR 256

// SMEM strides (floats) chosen for conflict-free mma fragment loads
#define KSTR 68           // bank = (4*g + t) -> all 32 distinct
#define VSTR 72           // bank = (8*t + g) -> all 32 distinct
#define QSTR 68

// SMEM layout (float offsets)
#define OFF_K 0
#define OFF_V (KR * KSTR)                 // 17408
#define OFF_Q (OFF_V + KR * VSTR)         // 35840
#define SM_FLOATS (OFF_Q + MQ * QSTR)     // 44544
#define SM_BYTES  (SM_FLOATS * 4)         // 178176

__device__ __forceinline__ uint32_t tf32_rna(float x) {
    uint32_t r;
    asm("cvt.rna.tf32.f32 %0, %1;" : "=r"(r) : "f"(x));
    return r;
}
__device__ __forceinline__ float ex2f(float x) {
    float y; asm("ex2.approx.ftz.f32 %0, %1;" : "=f"(y) : "f"(x)); return y;
}
// D = A(16x8 tf32) * B(8x8 tf32) + D, fp32 accumulate
__device__ __forceinline__ void mma_tf32(float d[4], const uint32_t a[4],
                                         uint32_t b0, uint32_t b1) {
    asm("mma.sync.aligned.m16n8k8.row.col.f32.tf32.tf32.f32 "
        "{%0,%1,%2,%3}, {%4,%5,%6,%7}, {%8,%9}, {%0,%1,%2,%3};"
        : "+f"(d[0]), "+f"(d[1]), "+f"(d[2]), "+f"(d[3])
        : "r"(a[0]), "r"(a[1]), "r"(a[2]), "r"(a[3]), "r"(b0), "r"(b1));
}

// Issue 16 QK MMAs for the 16-key tile at j0 into sacc[2 halves][4 chains][4].
// Chain depth 2 (ks and ks+4 share an accumulator); everything else independent.
#define QK_ISSUE(j0, sacc) do {                                               \
    _Pragma("unroll")                                                         \
    for (int u = 0; u < 2; u++) {                                             \
        _Pragma("unroll")                                                     \
        for (int c = 0; c < 4; c++)                                           \
            _Pragma("unroll")                                                 \
            for (int i = 0; i < 4; i++) sacc[u][c][i] = 0.f;                  \
        int kr = ((j0) + 8 * u + g) * KSTR + t;                               \
        _Pragma("unroll")                                                     \
        for (int ks = 0; ks < 8; ks++)                                        \
            mma_tf32(sacc[u][ks & 3], qa[ks],                                 \
                     Ku[kr + 8 * ks], Ku[kr + 8 * ks + 4]);                   \
    }                                                                         \
} while (0)

// Reduce + masked exp2 softmax + quad permute + PV for the tile at j0.
#define TILE_BODY(j0, sacc) do {                                              \
    uint32_t pa[2][4];                                                        \
    _Pragma("unroll")                                                         \
    for (int u = 0; u < 2; u++) {                                             \
        float s0 = (sacc[u][0][0] + sacc[u][1][0]) + (sacc[u][2][0] + sacc[u][3][0]); \
        float s1 = (sacc[u][0][1] + sacc[u][1][1]) + (sacc[u][2][1] + sacc[u][3][1]); \
        float s2 = (sacc[u][0][2] + sacc[u][1][2]) + (sacc[u][2][2] + sacc[u][3][2]); \
        float s3 = (sacc[u][0][3] + sacc[u][1][3]) + (sacc[u][2][3] + sacc[u][3][3]); \
        const int jc0 = (j0) + 8 * u + 2 * t, jc1 = jc0 + 1;                  \
        float p0 = (jc0 > qloc0 && jc0 <= qloc0 + WIN && jc0 >= jmin)         \
                     ? ex2f(s0 * cexp) : 0.f;                                 \
        float p1 = (jc1 > qloc0 && jc1 <= qloc0 + WIN && jc1 >= jmin)         \
                     ? ex2f(s1 * cexp) : 0.f;                                 \
        float p2 = (jc0 > qloc1 && jc0 <= qloc1 + WIN && jc0 >= jmin)         \
                     ? ex2f(s2 * cexp) : 0.f;                                 \
        float p3 = (jc1 > qloc1 && jc1 <= qloc1 + WIN && jc1 >= jmin)         \
                     ? ex2f(s3 * cexp) : 0.f;                                 \
        l0 += p0 + p1;                                                        \
        l1 += p2 + p3;                                                        \
        const int srcA = (lane & ~3) | (t >> 1);                              \
        const int srcB = srcA + 2;                                            \
        float x0 = __shfl_sync(0xFFFFFFFFu, p0, srcA);                        \
        float y0 = __shfl_sync(0xFFFFFFFFu, p1, srcA);                        \
        float x1 = __shfl_sync(0xFFFFFFFFu, p2, srcA);                        \
        float y1 = __shfl_sync(0xFFFFFFFFu, p3, srcA);                        \
        float x2 = __shfl_sync(0xFFFFFFFFu, p0, srcB);                        \
        float y2 = __shfl_sync(0xFFFFFFFFu, p1, srcB);                        \
        float x3 = __shfl_sync(0xFFFFFFFFu, p2, srcB);                        \
        float y3 = __shfl_sync(0xFFFFFFFFu, p3, srcB);                        \
        const bool odd = (t & 1);                                             \
        pa[u][0] = tf32_rna(odd ? y0 : x0);                                   \
        pa[u][1] = tf32_rna(odd ? y1 : x1);                                   \
        pa[u][2] = tf32_rna(odd ? y2 : x2);                                   \
        pa[u][3] = tf32_rna(odd ? y3 : x3);                                   \
    }                                                                         \
    {                                                                         \
        int va0 = ((j0) + t) * VSTR + g;                                      \
        int va1 = ((j0) + t + 4) * VSTR + g;                                  \
        int vb0 = ((j0) + 8 + t) * VSTR + g;                                  \
        int vb1 = ((j0) + 12 + t) * VSTR + g;                                 \
        _Pragma("unroll")                                                     \
        for (int f = 0; f < 8; f++) {                                         \
            mma_tf32(oacc[f], pa[0], Vu[va0 + 8 * f], Vu[va1 + 8 * f]);       \
            mma_tf32(oacc[f], pa[1], Vu[vb0 + 8 * f], Vu[vb1 + 8 * f]);       \
        }                                                                     \
    }                                                                         \
} while (0)

__global__ void __launch_bounds__(NTHR, 1)
local_attn_mma(const float* __restrict__ Q, const float* __restrict__ K,
               const float* __restrict__ V, float* __restrict__ O) {
    extern __shared__ float sm[];
    float* Ks = sm + OFF_K;
    float* Vs = sm + OFF_V;
    float* Qs = sm + OFF_Q;

    const int tid  = threadIdx.x;
    const int lane = tid & 31;
    const int wid  = tid >> 5;

    const int bid = blockIdx.x;           // 2048 = 8 * 8 * 32
    const int b   = bid >> 8;
    const int h   = (bid >> 5) & 7;
    const int q0  = (bid & 31) * MQ;
    const int kbase = q0 - WIN;

    // ---- cooperative loads, converting to tf32 at store time ----
    #pragma unroll 2
    for (int idx = tid; idx < MQ * 16; idx += NTHR) {
        int r = idx >> 4, c = idx & 15;
        float4 v = *reinterpret_cast<const float4*>(
            Q + ((size_t)(b * L_ + q0 + r) * H_ + h) * E_ + c * 4);
        uint4 u = make_uint4(tf32_rna(v.x), tf32_rna(v.y), tf32_rna(v.z), tf32_rna(v.w));
        *reinterpret_cast<uint4*>(Qs + r * QSTR + c * 4) = u;
    }
    #pragma unroll 4
    for (int idx = tid; idx < KR * 16; idx += NTHR) {
        int r = idx >> 4, c = idx & 15;
        int kg = kbase + r;
        float4 v = make_float4(0.f, 0.f, 0.f, 0.f);
        if (kg >= 0)
            v = *reinterpret_cast<const float4*>(
                K + ((size_t)(b * L_ + kg) * H_ + h) * E_ + c * 4);
        uint4 u = make_uint4(tf32_rna(v.x), tf32_rna(v.y), tf32_rna(v.z), tf32_rna(v.w));
        *reinterpret_cast<uint4*>(Ks + r * KSTR + c * 4) = u;
    }
    #pragma unroll 4
    for (int idx = tid; idx < KR * 16; idx += NTHR) {
        int r = idx >> 4, c = idx & 15;
        int kg = kbase + r;
        float4 v = make_float4(0.f, 0.f, 0.f, 0.f);
        if (kg >= 0)
            v = *reinterpret_cast<const float4*>(
                V + ((size_t)(b * L_ + kg) * H_ + h) * E_ + c * 4);
        uint4 u = make_uint4(tf32_rna(v.x), tf32_rna(v.y), tf32_rna(v.z), tf32_rna(v.w));
        *reinterpret_cast<uint4*>(Vs + r * VSTR + c * 4) = u;
    }
    __syncthreads();

    const int g = lane >> 2;              // row within fragment
    const int t = lane & 3;               // thread-in-group

    // ---- Q A-fragments for this warp's 16 queries ----
    uint32_t qa[8][4];
    {
        const uint32_t* Qu = reinterpret_cast<const uint32_t*>(Qs);
        int rbase = (16 * wid + g) * QSTR;
        #pragma unroll
        for (int ks = 0; ks < 8; ks++) {
            int c0 = 8 * ks + t;
            qa[ks][0] = Qu[rbase + c0];
            qa[ks][1] = Qu[rbase + 8 * QSTR + c0];
            qa[ks][2] = Qu[rbase + c0 + 4];
            qa[ks][3] = Qu[rbase + 8 * QSTR + c0 + 4];
        }
    }

    float oacc[8][4];
    #pragma unroll
    for (int f = 0; f < 8; f++)
        #pragma unroll
        for (int i = 0; i < 4; i++) oacc[f][i] = 0.f;

    float l0 = 0.f, l1 = 0.f;
    const int jmin  = (q0 == 0) ? WIN : 0;
    const int qloc0 = 16 * wid + g;
    const int qloc1 = qloc0 + 8;
    const float cexp = 0.18033688011112042f;   // log2(e) / 8

    const uint32_t* Ku = reinterpret_cast<const uint32_t*>(Ks);
    const uint32_t* Vu = reinterpret_cast<const uint32_t*>(Vs);

    // ---- main loop: 9 tiles of 16 keys, software-pipelined QK ----
    // Warp w needs tile-local keys [16w+1, 16w+143] -> tiles j0 = 16w + 16*it, it=0..8
    const int jbase = 16 * wid;
    float sA[2][4][4], sB[2][4][4];

    QK_ISSUE(jbase, sA);                       // prologue: QK(0)
    #pragma unroll
    for (int it = 0; it < 9; it++) {
        const int j0 = jbase + 16 * it;
        if ((it & 1) == 0) {
            if (it < 8) QK_ISSUE(j0 + 16, sB); // overlap next QK with this body
            TILE_BODY(j0, sA);
        } else {
            if (it < 8) QK_ISSUE(j0 + 16, sA);
            TILE_BODY(j0, sB);
        }
    }

    // ---- row-sum reduction across the lane quad, normalize, store ----
    l0 += __shfl_xor_sync(0xFFFFFFFFu, l0, 1);
    l0 += __shfl_xor_sync(0xFFFFFFFFu, l0, 2);
    l1 += __shfl_xor_sync(0xFFFFFFFFu, l1, 1);
    l1 += __shfl_xor_sync(0xFFFFFFFFu, l1, 2);
    const float inv0 = 1.0f / l0;
    const float inv1 = 1.0f / l1;

    float* o0 = O + ((size_t)(b * L_ + q0 + qloc0) * H_ + h) * E_;
    float* o1 = O + ((size_t)(b * L_ + q0 + qloc1) * H_ + h) * E_;
    #pragma unroll
    for (int f = 0; f < 8; f++) {
        int e = 8 * f + 2 * t;
        *reinterpret_cast<float2*>(o0 + e) =
            make_float2(oacc[f][0] * inv0, oacc[f][1] * inv0);
        *reinterpret_cast<float2*>(o1 + e) =
            make_float2(oacc[f][2] * inv1, oacc[f][3] * inv1);
    }
}

extern "C" void kernel_launch(void* const* d_in, const int* in_sizes, int n_in,
                              void* d_out, int out_size) {
    const float* Q = (const float*)d_in[0];
    const float* K = (const float*)d_in[1];
    const float* V = (const float*)d_in[2];
    float* O = (float*)d_out;

    cudaFuncSetAttribute(local_attn_mma,
                         cudaFuncAttributeMaxDynamicSharedMemorySize, SM_BYTES);

    dim3 grid(B_ * H_ * (L_ / MQ));   // 2048 CTAs
    dim3 block(NTHR);
    local_attn_mma<<<grid, block, SM_BYTES>>>(Q, K, V, O);
}

// round 13
// speedup vs baseline: 2.9812x; 1.2518x over previous
#include <cuda_runtime.h>
#include <cstdint>

// Problem constants
#define B_   8
#define L_   4096
#define H_   8
#define E_   64
#define WIN  128
#define MQ   128          // queries per CTA (8 row-groups x 16)
#define KR   256          // key rows per CTA: [q0-128, q0+128)
#define NTHR 512          // 16 warps: pair (w, w+8) shares rows, splits keys

// SMEM strides (floats) chosen for conflict-free mma fragment loads
#define KSTR 68           // bank = (4*g + t) -> all 32 distinct
#define VSTR 72           // bank = (8*t + g) -> all 32 distinct
#define QSTR 68

// SMEM layout (float offsets)
#define OFF_K 0
#define OFF_V (KR * KSTR)                 // 17408
#define OFF_Q (OFF_V + KR * VSTR)         // 35840
#define OFF_PB (OFF_Q + MQ * QSTR)        // 44544  partial (O,l) buffer
#define PBSTR 35                          // odd stride -> conflict-free
#define SM_FLOATS (OFF_PB + 8 * 32 * PBSTR)   // 53504
#define SM_BYTES  (SM_FLOATS * 4)             // 214016

__device__ __forceinline__ uint32_t tf32_rna(float x) {
    uint32_t r;
    asm("cvt.rna.tf32.f32 %0, %1;" : "=r"(r) : "f"(x));
    return r;
}
__device__ __forceinline__ float ex2f(float x) {
    float y; asm("ex2.approx.ftz.f32 %0, %1;" : "=f"(y) : "f"(x)); return y;
}
// D = A(16x8 tf32) * B(8x8 tf32) + D, fp32 accumulate
__device__ __forceinline__ void mma_tf32(float d[4], const uint32_t a[4],
                                         uint32_t b0, uint32_t b1) {
    asm("mma.sync.aligned.m16n8k8.row.col.f32.tf32.tf32.f32 "
        "{%0,%1,%2,%3}, {%4,%5,%6,%7}, {%8,%9}, {%0,%1,%2,%3};"
        : "+f"(d[0]), "+f"(d[1]), "+f"(d[2]), "+f"(d[3])
        : "r"(a[0]), "r"(a[1]), "r"(a[2]), "r"(a[3]), "r"(b0), "r"(b1));
}

// 16 QK MMAs for the 16-key tile at j0 into sacc[2 halves][2 chains][4].
// Chain depth 4; consecutive MMAs alternate chains (independent back-to-back).
#define QK_ISSUE(j0, sacc) do {                                               \
    _Pragma("unroll")                                                         \
    for (int u = 0; u < 2; u++) {                                             \
        _Pragma("unroll")                                                     \
        for (int c = 0; c < 2; c++)                                           \
            _Pragma("unroll")                                                 \
            for (int i = 0; i < 4; i++) sacc[u][c][i] = 0.f;                  \
        int kr = ((j0) + 8 * u + g) * KSTR + t;                               \
        _Pragma("unroll")                                                     \
        for (int ks = 0; ks < 8; ks++)                                        \
            mma_tf32(sacc[u][ks & 1], qa[ks],                                 \
                     Ku[kr + 8 * ks], Ku[kr + 8 * ks + 4]);                   \
    }                                                                         \
} while (0)

// Reduce + masked exp2 softmax + quad permute + PV for the tile at j0.
// (log2(e)/8 scale is pre-folded into Q, so p = ex2(s) directly.)
#define TILE_BODY(j0, sacc) do {                                              \
    uint32_t pa[2][4];                                                        \
    _Pragma("unroll")                                                         \
    for (int u = 0; u < 2; u++) {                                             \
        float s0 = sacc[u][0][0] + sacc[u][1][0];                             \
        float s1 = sacc[u][0][1] + sacc[u][1][1];                             \
        float s2 = sacc[u][0][2] + sacc[u][1][2];                             \
        float s3 = sacc[u][0][3] + sacc[u][1][3];                             \
        const int jc0 = (j0) + 8 * u + 2 * t, jc1 = jc0 + 1;                  \
        float p0 = (jc0 > qloc0 && jc0 <= qloc0 + WIN && jc0 >= jmin)         \
                     ? ex2f(s0) : 0.f;                                        \
        float p1 = (jc1 > qloc0 && jc1 <= qloc0 + WIN && jc1 >= jmin)         \
                     ? ex2f(s1) : 0.f;                                        \
        float p2 = (jc0 > qloc1 && jc0 <= qloc1 + WIN && jc0 >= jmin)         \
                     ? ex2f(s2) : 0.f;                                        \
        float p3 = (jc1 > qloc1 && jc1 <= qloc1 + WIN && jc1 >= jmin)         \
                     ? ex2f(s3) : 0.f;                                        \
        l0 += p0 + p1;                                                        \
        l1 += p2 + p3;                                                        \
        const int srcA = (lane & ~3) | (t >> 1);                              \
        const int srcB = srcA + 2;                                            \
        float x0 = __shfl_sync(0xFFFFFFFFu, p0, srcA);                        \
        float y0 = __shfl_sync(0xFFFFFFFFu, p1, srcA);                        \
        float x1 = __shfl_sync(0xFFFFFFFFu, p2, srcA);                        \
        float y1 = __shfl_sync(0xFFFFFFFFu, p3, srcA);                        \
        float x2 = __shfl_sync(0xFFFFFFFFu, p0, srcB);                        \
        float y2 = __shfl_sync(0xFFFFFFFFu, p1, srcB);                        \
        float x3 = __shfl_sync(0xFFFFFFFFu, p2, srcB);                        \
        float y3 = __shfl_sync(0xFFFFFFFFu, p3, srcB);                        \
        const bool odd = (t & 1);                                             \
        pa[u][0] = tf32_rna(odd ? y0 : x0);                                   \
        pa[u][1] = tf32_rna(odd ? y1 : x1);                                   \
        pa[u][2] = tf32_rna(odd ? y2 : x2);                                   \
        pa[u][3] = tf32_rna(odd ? y3 : x3);                                   \
    }                                                                         \
    {                                                                         \
        int va0 = ((j0) + t) * VSTR + g;                                      \
        int va1 = ((j0) + t + 4) * VSTR + g;                                  \
        int vb0 = ((j0) + 8 + t) * VSTR + g;                                  \
        int vb1 = ((j0) + 12 + t) * VSTR + g;                                 \
        _Pragma("unroll")                                                     \
        for (int f = 0; f < 8; f++) {                                         \
            mma_tf32(oacc[f], pa[0], Vu[va0 + 8 * f], Vu[va1 + 8 * f]);       \
            mma_tf32(oacc[f], pa[1], Vu[vb0 + 8 * f], Vu[vb1 + 8 * f]);       \
        }                                                                     \
    }                                                                         \
} while (0)

// Pipelined run over ITCNT tiles starting at tile index ITLO (constants).
#define RUN_TILES(ITLO, ITCNT) do {                                           \
    QK_ISSUE(jbase + 16 * (ITLO), sA);                                        \
    _Pragma("unroll")                                                         \
    for (int ii = 0; ii < (ITCNT); ii++) {                                    \
        const int j0 = jbase + 16 * ((ITLO) + ii);                            \
        if ((ii & 1) == 0) {                                                  \
            if (ii + 1 < (ITCNT)) QK_ISSUE(j0 + 16, sB);                      \
            TILE_BODY(j0, sA);                                                \
        } else {                                                              \
            if (ii + 1 < (ITCNT)) QK_ISSUE(j0 + 16, sA);                      \
            TILE_BODY(j0, sB);                                                \
        }                                                                     \
    }                                                                         \
} while (0)

__global__ void __launch_bounds__(NTHR, 1)
local_attn_mma(const float* __restrict__ Q, const float* __restrict__ K,
               const float* __restrict__ V, float* __restrict__ O) {
    extern __shared__ float sm[];
    float* Ks = sm + OFF_K;
    float* Vs = sm + OFF_V;
    float* Qs = sm + OFF_Q;

    const int tid  = threadIdx.x;
    const int lane = tid & 31;
    const int wid  = tid >> 5;

    const int bid = blockIdx.x;           // 2048 = 8 * 8 * 32
    const int b   = bid >> 8;
    const int h   = (bid >> 5) & 7;
    const int q0  = (bid & 31) * MQ;
    const int kbase = q0 - WIN;

    const float cexp = 0.18033688011112042f;   // log2(e) / 8, folded into Q

    // ---- cooperative loads, converting to tf32 at store time ----
    #pragma unroll 2
    for (int idx = tid; idx < MQ * 16; idx += NTHR) {
        int r = idx >> 4, c = idx & 15;
        float4 v = *reinterpret_cast<const float4*>(
            Q + ((size_t)(b * L_ + q0 + r) * H_ + h) * E_ + c * 4);
        uint4 u = make_uint4(tf32_rna(v.x * cexp), tf32_rna(v.y * cexp),
                             tf32_rna(v.z * cexp), tf32_rna(v.w * cexp));
        *reinterpret_cast<uint4*>(Qs + r * QSTR + c * 4) = u;
    }
    #pragma unroll 4
    for (int idx = tid; idx < KR * 16; idx += NTHR) {
        int r = idx >> 4, c = idx & 15;
        int kg = kbase + r;
        float4 v = make_float4(0.f, 0.f, 0.f, 0.f);
        if (kg >= 0)
            v = *reinterpret_cast<const float4*>(
                K + ((size_t)(b * L_ + kg) * H_ + h) * E_ + c * 4);
        uint4 u = make_uint4(tf32_rna(v.x), tf32_rna(v.y), tf32_rna(v.z), tf32_rna(v.w));
        *reinterpret_cast<uint4*>(Ks + r * KSTR + c * 4) = u;
    }
    #pragma unroll 4
    for (int idx = tid; idx < KR * 16; idx += NTHR) {
        int r = idx >> 4, c = idx & 15;
        int kg = kbase + r;
        float4 v = make_float4(0.f, 0.f, 0.f, 0.f);
        if (kg >= 0)
            v = *reinterpret_cast<const float4*>(
                V + ((size_t)(b * L_ + kg) * H_ + h) * E_ + c * 4);
        uint4 u = make_uint4(tf32_rna(v.x), tf32_rna(v.y), tf32_rna(v.z), tf32_rna(v.w));
        *reinterpret_cast<uint4*>(Vs + r * VSTR + c * 4) = u;
    }
    __syncthreads();

    const int g  = lane >> 2;             // row within fragment
    const int t  = lane & 3;              // thread-in-group
    const int rg = wid & 7;               // row group (shared by warp pair)

    // ---- Q A-fragments for this row group's 16 queries ----
    uint32_t qa[8][4];
    {
        const uint32_t* Qu = reinterpret_cast<const uint32_t*>(Qs);
        int rbase = (16 * rg + g) * QSTR;
        #pragma unroll
        for (int ks = 0; ks < 8; ks++) {
            int c0 = 8 * ks + t;
            qa[ks][0] = Qu[rbase + c0];
            qa[ks][1] = Qu[rbase + 8 * QSTR + c0];
            qa[ks][2] = Qu[rbase + c0 + 4];
            qa[ks][3] = Qu[rbase + 8 * QSTR + c0 + 4];
        }
    }

    float oacc[8][4];
    #pragma unroll
    for (int f = 0; f < 8; f++)
        #pragma unroll
        for (int i = 0; i < 4; i++) oacc[f][i] = 0.f;

    float l0 = 0.f, l1 = 0.f;
    const int jmin  = (q0 == 0) ? WIN : 0;
    const int qloc0 = 16 * rg + g;
    const int qloc1 = qloc0 + 8;

    const uint32_t* Ku = reinterpret_cast<const uint32_t*>(Ks);
    const uint32_t* Vu = reinterpret_cast<const uint32_t*>(Vs);

    // ---- main loop: row group needs tiles 0..8; pair splits 4 / 5 ----
    const int jbase = 16 * rg;
    float sA[2][2][4], sB[2][2][4];

    if (wid < 8) { RUN_TILES(0, 4); }
    else         { RUN_TILES(4, 5); }

    // ---- combine partner partials via SMEM, then normalize + store ----
    if (wid >= 8) {
        float* pb = sm + OFF_PB + ((wid - 8) * 32 + lane) * PBSTR;
        #pragma unroll
        for (int f = 0; f < 8; f++) {
            pb[4 * f + 0] = oacc[f][0];
            pb[4 * f + 1] = oacc[f][1];
            pb[4 * f + 2] = oacc[f][2];
            pb[4 * f + 3] = oacc[f][3];
        }
        pb[32] = l0;
        pb[33] = l1;
    }
    __syncthreads();
    if (wid < 8) {
        const float* pb = sm + OFF_PB + (wid * 32 + lane) * PBSTR;
        #pragma unroll
        for (int f = 0; f < 8; f++) {
            oacc[f][0] += pb[4 * f + 0];
            oacc[f][1] += pb[4 * f + 1];
            oacc[f][2] += pb[4 * f + 2];
            oacc[f][3] += pb[4 * f + 3];
        }
        l0 += pb[32];
        l1 += pb[33];

        // row-sum reduction across the lane quad
        l0 += __shfl_xor_sync(0xFFFFFFFFu, l0, 1);
        l0 += __shfl_xor_sync(0xFFFFFFFFu, l0, 2);
        l1 += __shfl_xor_sync(0xFFFFFFFFu, l1, 1);
        l1 += __shfl_xor_sync(0xFFFFFFFFu, l1, 2);
        const float inv0 = 1.0f / l0;
        const float inv1 = 1.0f / l1;

        float* o0 = O + ((size_t)(b * L_ + q0 + qloc0) * H_ + h) * E_;
        float* o1 = O + ((size_t)(b * L_ + q0 + qloc1) * H_ + h) * E_;
        #pragma unroll
        for (int f = 0; f < 8; f++) {
            int e = 8 * f + 2 * t;
            *reinterpret_cast<float2*>(o0 + e) =
                make_float2(oacc[f][0] * inv0, oacc[f][1] * inv0);
            *reinterpret_cast<float2*>(o1 + e) =
                make_float2(oacc[f][2] * inv1, oacc[f][3] * inv1);
        }
    }
}

extern "C" void kernel_launch(void* const* d_in, const int* in_sizes, int n_in,
                              void* d_out, int out_size) {
    const float* Q = (const float*)d_in[0];
    const float* K = (const float*)d_in[1];
    const float* V = (const float*)d_in[2];
    float* O = (float*)d_out;

    cudaFuncSetAttribute(local_attn_mma,
                         cudaFuncAttributeMaxDynamicSharedMemorySize, SM_BYTES);

    dim3 grid(B_ * H_ * (L_ / MQ));   // 2048 CTAs
    dim3 block(NTHR);
    local_attn_mma<<<grid, block, SM_BYTES>>>(Q, K, V, O);
}

// round 14
// speedup vs baseline: 3.2992x; 1.1067x over previous
#include <cuda_runtime.h>
#include <cstdint>

// Problem constants
#define B_   8
#define L_   4096
#define H_   8
#define E_   64
#define WIN  128
#define MQ   64           // queries per CTA (4 row-groups x 16)
#define KR   192          // key rows per CTA: [q0-128, q0+64)
#define NTHR 256          // 8 warps: pair (w, w+4) shares rows, splits keys

// Pad-free swizzled SMEM layout (float offsets).
//  K,Q: col' = col ^ (4*(row&7))   V: col' = col ^ (8*(row&3))
#define OFF_K 0
#define OFF_V (KR * E_)                   // 12288
#define OFF_Q (OFF_V + KR * E_)           // 24576
#define SM_FLOATS (OFF_Q + MQ * E_)       // 28672
#define SM_BYTES  (SM_FLOATS * 4)         // 114688  -> 2 CTAs/SM
#define OFF_PB OFF_K                      // partial buffer reuses K region post-loop
#define PBSTR 35

__device__ __forceinline__ uint32_t tf32_rna(float x) {
    uint32_t r;
    asm("cvt.rna.tf32.f32 %0, %1;" : "=r"(r) : "f"(x));
    return r;
}
__device__ __forceinline__ float ex2f(float x) {
    float y; asm("ex2.approx.ftz.f32 %0, %1;" : "=f"(y) : "f"(x)); return y;
}
// D = A(16x8 tf32) * B(8x8 tf32) + D, fp32 accumulate
__device__ __forceinline__ void mma_tf32(float d[4], const uint32_t a[4],
                                         uint32_t b0, uint32_t b1) {
    asm("mma.sync.aligned.m16n8k8.row.col.f32.tf32.tf32.f32 "
        "{%0,%1,%2,%3}, {%4,%5,%6,%7}, {%8,%9}, {%0,%1,%2,%3};"
        : "+f"(d[0]), "+f"(d[1]), "+f"(d[2]), "+f"(d[3])
        : "r"(a[0]), "r"(a[1]), "r"(a[2]), "r"(a[3]), "r"(b0), "r"(b1));
}

// 16 QK MMAs for the 16-key tile at j0 into sacc[2 halves][2 chains][4].
#define QK_ISSUE(j0, sacc) do {                                               \
    _Pragma("unroll")                                                         \
    for (int u = 0; u < 2; u++) {                                             \
        _Pragma("unroll")                                                     \
        for (int c = 0; c < 2; c++)                                           \
            _Pragma("unroll")                                                 \
            for (int i = 0; i < 4; i++) sacc[u][c][i] = 0.f;                  \
        const int krow = ((j0) + 8 * u + g) * E_;                             \
        _Pragma("unroll")                                                     \
        for (int ks = 0; ks < 8; ks++) {                                      \
            const int c0 = (8 * ks + t) ^ g4;                                 \
            const int c1 = (8 * ks + t + 4) ^ g4;                             \
            mma_tf32(sacc[u][ks & 1], qa[ks], Ku[krow + c0], Ku[krow + c1]);  \
        }                                                                     \
    }                                                                         \
} while (0)

// Reduce + masked exp2 softmax + quad permute + PV for the tile at j0.
#define TILE_BODY(j0, sacc) do {                                              \
    uint32_t pa[2][4];                                                        \
    _Pragma("unroll")                                                         \
    for (int u = 0; u < 2; u++) {                                             \
        float s0 = sacc[u][0][0] + sacc[u][1][0];                             \
        float s1 = sacc[u][0][1] + sacc[u][1][1];                             \
        float s2 = sacc[u][0][2] + sacc[u][1][2];                             \
        float s3 = sacc[u][0][3] + sacc[u][1][3];                             \
        const int jc0 = (j0) + 8 * u + 2 * t, jc1 = jc0 + 1;                  \
        float p0 = (jc0 > qloc0 && jc0 <= qloc0 + WIN && jc0 >= jmin)         \
                     ? ex2f(s0) : 0.f;                                        \
        float p1 = (jc1 > qloc0 && jc1 <= qloc0 + WIN && jc1 >= jmin)         \
                     ? ex2f(s1) : 0.f;                                        \
        float p2 = (jc0 > qloc1 && jc0 <= qloc1 + WIN && jc0 >= jmin)         \
                     ? ex2f(s2) : 0.f;                                        \
        float p3 = (jc1 > qloc1 && jc1 <= qloc1 + WIN && jc1 >= jmin)         \
                     ? ex2f(s3) : 0.f;                                        \
        l0 += p0 + p1;                                                        \
        l1 += p2 + p3;                                                        \
        const int srcA = (lane & ~3) | (t >> 1);                              \
        const int srcB = srcA + 2;                                            \
        float x0 = __shfl_sync(0xFFFFFFFFu, p0, srcA);                        \
        float y0 = __shfl_sync(0xFFFFFFFFu, p1, srcA);                        \
        float x1 = __shfl_sync(0xFFFFFFFFu, p2, srcA);                        \
        float y1 = __shfl_sync(0xFFFFFFFFu, p3, srcA);                        \
        float x2 = __shfl_sync(0xFFFFFFFFu, p0, srcB);                        \
        float y2 = __shfl_sync(0xFFFFFFFFu, p1, srcB);                        \
        float x3 = __shfl_sync(0xFFFFFFFFu, p2, srcB);                        \
        float y3 = __shfl_sync(0xFFFFFFFFu, p3, srcB);                        \
        const bool odd = (t & 1);                                             \
        pa[u][0] = tf32_rna(odd ? y0 : x0);                                   \
        pa[u][1] = tf32_rna(odd ? y1 : x1);                                   \
        pa[u][2] = tf32_rna(odd ? y2 : x2);                                   \
        pa[u][3] = tf32_rna(odd ? y3 : x3);                                   \
    }                                                                         \
    {                                                                         \
        const int ra = ((j0) + t) * E_ + g;                                   \
        const int rb = ((j0) + t + 4) * E_ + g;                               \
        const int rc = ((j0) + 8 + t) * E_ + g;                               \
        const int rd = ((j0) + 12 + t) * E_ + g;                              \
        _Pragma("unroll")                                                     \
        for (int f = 0; f < 8; f++) {                                         \
            const int off = (f << 3) ^ t8;                                    \
            mma_tf32(oacc[f], pa[0], Vu[ra + off], Vu[rb + off]);             \
            mma_tf32(oacc[f], pa[1], Vu[rc + off], Vu[rd + off]);             \
        }                                                                     \
    }                                                                         \
} while (0)

// Pipelined run over ITCNT tiles starting at tile index ITLO (constants).
#define RUN_TILES(ITLO, ITCNT) do {                                           \
    QK_ISSUE(jbase + 16 * (ITLO), sA);                                        \
    _Pragma("unroll")                                                         \
    for (int ii = 0; ii < (ITCNT); ii++) {                                    \
        const int j0 = jbase + 16 * ((ITLO) + ii);                            \
        if ((ii & 1) == 0) {                                                  \
            if (ii + 1 < (ITCNT)) QK_ISSUE(j0 + 16, sB);                      \
            TILE_BODY(j0, sA);                                                \
        } else {                                                              \
            if (ii + 1 < (ITCNT)) QK_ISSUE(j0 + 16, sA);                      \
            TILE_BODY(j0, sB);                                                \
        }                                                                     \
    }                                                                         \
} while (0)

__global__ void __launch_bounds__(NTHR, 2)
local_attn_mma(const float* __restrict__ Q, const float* __restrict__ K,
               const float* __restrict__ V, float* __restrict__ O) {
    extern __shared__ float sm[];
    float* Ks = sm + OFF_K;
    float* Vs = sm + OFF_V;
    float* Qs = sm + OFF_Q;

    const int tid  = threadIdx.x;
    const int lane = tid & 31;
    const int wid  = tid >> 5;

    const int bid = blockIdx.x;           // 4096 = 8b * 8h * 64 tiles
    const int b   = bid >> 9;
    const int h   = (bid >> 6) & 7;
    const int q0  = (bid & 63) * MQ;
    const int kbase = q0 - WIN;

    const float cexp = 0.18033688011112042f;   // log2(e)/8, folded into Q

    // ---- cooperative loads -> tf32 -> swizzled SMEM ----
    // Q [64][64]: chunk' = cc ^ (r&7)
    #pragma unroll
    for (int idx = tid; idx < MQ * 16; idx += NTHR) {
        int r = idx >> 4, cc = idx & 15;
        float4 v = *reinterpret_cast<const float4*>(
            Q + ((size_t)(b * L_ + q0 + r) * H_ + h) * E_ + cc * 4);
        uint4 u = make_uint4(tf32_rna(v.x * cexp), tf32_rna(v.y * cexp),
                             tf32_rna(v.z * cexp), tf32_rna(v.w * cexp));
        *reinterpret_cast<uint4*>(Qs + r * E_ + 4 * (cc ^ (r & 7))) = u;
    }
    // K [192][64]: chunk' = cc ^ (r&7)
    #pragma unroll
    for (int idx = tid; idx < KR * 16; idx += NTHR) {
        int r = idx >> 4, cc = idx & 15;
        int kg = kbase + r;
        float4 v = make_float4(0.f, 0.f, 0.f, 0.f);
        if (kg >= 0)
            v = *reinterpret_cast<const float4*>(
                K + ((size_t)(b * L_ + kg) * H_ + h) * E_ + cc * 4);
        uint4 u = make_uint4(tf32_rna(v.x), tf32_rna(v.y), tf32_rna(v.z), tf32_rna(v.w));
        *reinterpret_cast<uint4*>(Ks + r * E_ + 4 * (cc ^ (r & 7))) = u;
    }
    // V [192][64]: chunk' = cc ^ (2*(r&3))
    #pragma unroll
    for (int idx = tid; idx < KR * 16; idx += NTHR) {
        int r = idx >> 4, cc = idx & 15;
        int kg = kbase + r;
        float4 v = make_float4(0.f, 0.f, 0.f, 0.f);
        if (kg >= 0)
            v = *reinterpret_cast<const float4*>(
                V + ((size_t)(b * L_ + kg) * H_ + h) * E_ + cc * 4);
        uint4 u = make_uint4(tf32_rna(v.x), tf32_rna(v.y), tf32_rna(v.z), tf32_rna(v.w));
        *reinterpret_cast<uint4*>(Vs + r * E_ + 4 * (cc ^ (2 * (r & 3)))) = u;
    }
    __syncthreads();

    const int g  = lane >> 2;             // row within fragment
    const int t  = lane & 3;              // thread-in-group
    const int g4 = g << 2;                // K/Q swizzle term
    const int t8 = t << 3;                // V swizzle term
    const int rg = wid & 3;               // row group (shared by warp pair)

    // ---- Q A-fragments for this row group's 16 queries ----
    uint32_t qa[8][4];
    {
        const uint32_t* Qu = reinterpret_cast<const uint32_t*>(Qs);
        int rbase = (16 * rg + g) * E_;
        #pragma unroll
        for (int ks = 0; ks < 8; ks++) {
            const int c0 = (8 * ks + t) ^ g4;
            const int c1 = (8 * ks + t + 4) ^ g4;
            qa[ks][0] = Qu[rbase + c0];
            qa[ks][1] = Qu[rbase + 8 * E_ + c0];
            qa[ks][2] = Qu[rbase + c1];
            qa[ks][3] = Qu[rbase + 8 * E_ + c1];
        }
    }

    float oacc[8][4];
    #pragma unroll
    for (int f = 0; f < 8; f++)
        #pragma unroll
        for (int i = 0; i < 4; i++) oacc[f][i] = 0.f;

    float l0 = 0.f, l1 = 0.f;
    const int jmin  = (q0 < WIN) ? (WIN - q0) : 0;   // mask keys < 0 (tile-local)
    const int qloc0 = 16 * rg + g;
    const int qloc1 = qloc0 + 8;

    const uint32_t* Ku = reinterpret_cast<const uint32_t*>(Ks);
    const uint32_t* Vu = reinterpret_cast<const uint32_t*>(Vs);

    // ---- main loop: row group needs tiles 0..8; pair splits 4 / 5 ----
    const int jbase = 16 * rg;
    float sA[2][2][4], sB[2][2][4];

    if (wid < 4) { RUN_TILES(0, 4); }
    else         { RUN_TILES(4, 5); }

    // ---- combine partner partials (buffer reuses dead K region) ----
    __syncthreads();                      // all K reads complete
    if (wid >= 4) {
        float* pb = sm + OFF_PB + ((wid - 4) * 32 + lane) * PBSTR;
        #pragma unroll
        for (int f = 0; f < 8; f++) {
            pb[4 * f + 0] = oacc[f][0];
            pb[4 * f + 1] = oacc[f][1];
            pb[4 * f + 2] = oacc[f][2];
            pb[4 * f + 3] = oacc[f][3];
        }
        pb[32] = l0;
        pb[33] = l1;
    }
    __syncthreads();
    if (wid < 4) {
        const float* pb = sm + OFF_PB + (wid * 32 + lane) * PBSTR;
        #pragma unroll
        for (int f = 0; f < 8; f++) {
            oacc[f][0] += pb[4 * f + 0];
            oacc[f][1] += pb[4 * f + 1];
            oacc[f][2] += pb[4 * f + 2];
            oacc[f][3] += pb[4 * f + 3];
        }
        l0 += pb[32];
        l1 += pb[33];

        // row-sum reduction across the lane quad
        l0 += __shfl_xor_sync(0xFFFFFFFFu, l0, 1);
        l0 += __shfl_xor_sync(0xFFFFFFFFu, l0, 2);
        l1 += __shfl_xor_sync(0xFFFFFFFFu, l1, 1);
        l1 += __shfl_xor_sync(0xFFFFFFFFu, l1, 2);
        const float inv0 = 1.0f / l0;
        const float inv1 = 1.0f / l1;

        float* o0 = O + ((size_t)(b * L_ + q0 + qloc0) * H_ + h) * E_;
        float* o1 = O + ((size_t)(b * L_ + q0 + qloc1) * H_ + h) * E_;
        #pragma unroll
        for (int f = 0; f < 8; f++) {
            int e = 8 * f + 2 * t;
            *reinterpret_cast<float2*>(o0 + e) =
                make_float2(oacc[f][0] * inv0, oacc[f][1] * inv0);
            *reinterpret_cast<float2*>(o1 + e) =
                make_float2(oacc[f][2] * inv1, oacc[f][3] * inv1);
        }
    }
}

extern "C" void kernel_launch(void* const* d_in, const int* in_sizes, int n_in,
                              void* d_out, int out_size) {
    const float* Q = (const float*)d_in[0];
    const float* K = (const float*)d_in[1];
    const float* V = (const float*)d_in[2];
    float* O = (float*)d_out;

    cudaFuncSetAttribute(local_attn_mma,
                         cudaFuncAttributeMaxDynamicSharedMemorySize, SM_BYTES);

    dim3 grid(B_ * H_ * (L_ / MQ));   // 4096 CTAs
    dim3 block(NTHR);
    local_attn_mma<<<grid, block, SM_BYTES>>>(Q, K, V, O);
}